// round 5
// baseline (speedup 1.0000x reference)
#include <cuda_runtime.h>
#include <cstdint>

#define N_NODES 8192
#define C_CLS   16
#define ROWS_PER_BLK 256          // 128 row-pairs
#define COLS_PER_BLK 128
#define TPB 128
#define NBX (N_NODES / COLS_PER_BLK)   // 64
#define NBY (N_NODES / ROWS_PER_BLK)   // 32
#define NBLK (NBX * NBY)               // 2048
#define NPAIR (ROWS_PER_BLK / 2)       // 128

// Table geometry (bytes): entry = 16 floats padded to 80B so the 4 entries of a
// pair start at {0,80,160,240} mod 128 -> disjoint banks for LDS.128 fan-out.
#define ENTRY_B 80
#define PAIR_B  (4 * ENTRY_B)          // 320
#define TBL_FLOATS (NPAIR * PAIR_B / 4)  // 10240 floats = 40KB

// SoA per-block partials + completion ticket (module-load zeroed; ticket self-resets).
__device__ float g_quadp[NBLK];
__device__ float g_degp[NBLK];
__device__ float g_dHp[C_CLS][NBLK];
__device__ unsigned int g_count;

__global__ void __launch_bounds__(TPB) mm_fused(const float* __restrict__ A,
                                                const float* __restrict__ H,
                                                float* __restrict__ out) {
    __shared__ __align__(16) float tbl[TBL_FLOATS];   // 40 KB pair table
    __shared__ float s_dH[C_CLS];
    __shared__ float s_quad;
    __shared__ unsigned int s_deg;
    __shared__ int s_islast;

    const int t = threadIdx.x;
    const int colbase = blockIdx.x * COLS_PER_BLK;
    const int rowbase = blockIdx.y * ROWS_PER_BLK;

    if (t < C_CLS) s_dH[t] = 0.f;
    if (t == 0) { s_quad = 0.f; s_deg = 0u; s_islast = 0; }

    // ---- Build pair table: entries {0, H_r1, H_r0, H_r0+H_r1} per row pair ----
    {
        // thread t owns pair t (NPAIR == TPB)
        const float4* hr = reinterpret_cast<const float4*>(
            H + (size_t)(rowbase + 2 * t) * C_CLS);   // 2 adjacent rows = 8 float4
        float4 h0[4], h1[4];
        #pragma unroll
        for (int k = 0; k < 4; k++) { h0[k] = hr[k]; h1[k] = hr[4 + k]; }
        char* base = reinterpret_cast<char*>(tbl) + t * PAIR_B;
        float4* e0 = reinterpret_cast<float4*>(base);
        float4* e1 = reinterpret_cast<float4*>(base + ENTRY_B);
        float4* e2 = reinterpret_cast<float4*>(base + 2 * ENTRY_B);
        float4* e3 = reinterpret_cast<float4*>(base + 3 * ENTRY_B);
        #pragma unroll
        for (int k = 0; k < 4; k++) {
            e0[k] = make_float4(0.f, 0.f, 0.f, 0.f);
            e1[k] = h1[k];
            e2[k] = h0[k];
            e3[k] = make_float4(h0[k].x + h1[k].x, h0[k].y + h1[k].y,
                                h0[k].z + h1[k].z, h0[k].w + h1[k].w);
        }
    }
    __syncthreads();

    // ---- Main loop: lane owns 1 column; process row pairs with MLP=8 ----
    const int c = colbase + t;
    const float* __restrict__ ar = A + (size_t)rowbase * N_NODES + c;
    const char* __restrict__ tb = reinterpret_cast<const char*>(tbl);

    unsigned long long acc[8];   // packed f32x2: x[c, 0..15]
    #pragma unroll
    for (int k = 0; k < 8; k++) acc[k] = 0ull;
    unsigned int deg = 0;

    for (int rp = 0; rp < NPAIR; rp += 4) {
        float av0[4], av1[4];
        #pragma unroll
        for (int u = 0; u < 4; u++) {   // 8 independent LDGs up front
            av0[u] = __ldg(ar + (size_t)(2 * (rp + u))     * N_NODES);
            av1[u] = __ldg(ar + (size_t)(2 * (rp + u) + 1) * N_NODES);
        }
        #pragma unroll
        for (int u = 0; u < 4; u++) {
            unsigned int p0 = (av0[u] > 0.f);
            unsigned int p1 = (av1[u] > 0.f);
            deg += p0 + p1;
            unsigned int off = (unsigned)(rp + u) * PAIR_B + (p0 * 2u + p1) * ENTRY_B;
            const ulonglong2* ep = reinterpret_cast<const ulonglong2*>(tb + off);
            #pragma unroll
            for (int k = 0; k < 4; k++) {
                ulonglong2 h = ep[k];   // LDS.128, <=4 distinct addrs, bank-disjoint
                asm("add.rn.f32x2 %0, %1, %0;" : "+l"(acc[2 * k])     : "l"(h.x));
                asm("add.rn.f32x2 %0, %1, %0;" : "+l"(acc[2 * k + 1]) : "l"(h.y));
            }
        }
    }

    // ---- Epilogue: quad += x[c].H[c] ; dH += deg_c * H[c,:] ----
    const float* __restrict__ hc = H + (size_t)c * C_CLS;
    float q = 0.f;
    #pragma unroll
    for (int k = 0; k < 8; k++) {
        float lo = __uint_as_float((unsigned int)(acc[k] & 0xffffffffull));
        float hi = __uint_as_float((unsigned int)(acc[k] >> 32));
        q += lo * hc[2 * k] + hi * hc[2 * k + 1];
    }
    atomicAdd(&s_quad, q);
    atomicAdd(&s_deg, deg);
    const float fd = (float)deg;
    #pragma unroll
    for (int k = 0; k < C_CLS; k++) atomicAdd(&s_dH[k], fd * hc[k]);
    __syncthreads();

    // ---- Publish partials (thread 0 only, then release via ticket) ----
    const int bid = blockIdx.y * gridDim.x + blockIdx.x;
    if (t == 0) {
        g_quadp[bid] = s_quad;
        g_degp[bid] = (float)s_deg;
        #pragma unroll
        for (int k = 0; k < C_CLS; k++) g_dHp[k][bid] = s_dH[k];
        __threadfence();
        unsigned int ticket = atomicAdd(&g_count, 1u);
        s_islast = (ticket == NBLK - 1);
    }
    __syncthreads();
    if (!s_islast) return;

    // ---- Last block: final reduction over all 2048 partials ----
    __threadfence();
    __shared__ double r_acc[C_CLS + 2];
    if (t < C_CLS + 2) r_acc[t] = 0.0;
    __syncthreads();

    double lq = 0.0, ls = 0.0, ldh[C_CLS];
    #pragma unroll
    for (int k = 0; k < C_CLS; k++) ldh[k] = 0.0;
    for (int slot = t; slot < NBLK; slot += TPB) {   // coalesced SoA reads
        lq += (double)g_quadp[slot];
        ls += (double)g_degp[slot];
        #pragma unroll
        for (int k = 0; k < C_CLS; k++) ldh[k] += (double)g_dHp[k][slot];
    }
    #pragma unroll
    for (int o = 16; o > 0; o >>= 1) {
        lq += __shfl_xor_sync(0xffffffffu, lq, o);
        ls += __shfl_xor_sync(0xffffffffu, ls, o);
        #pragma unroll
        for (int k = 0; k < C_CLS; k++)
            ldh[k] += __shfl_xor_sync(0xffffffffu, ldh[k], o);
    }
    if ((t & 31) == 0) {
        atomicAdd(&r_acc[0], lq);
        atomicAdd(&r_acc[1], ls);
        #pragma unroll
        for (int k = 0; k < C_CLS; k++) atomicAdd(&r_acc[2 + k], ldh[k]);
    }
    __syncthreads();
    if (t == 0) {
        double quad = r_acc[0], s = r_acc[1], d = 0.0;
        #pragma unroll
        for (int k = 0; k < C_CLS; k++) d += r_acc[2 + k] * r_acc[2 + k];
        out[0] = (float)((quad - d / s) / s);
        g_count = 0;   // reset for next graph replay
    }
}

extern "C" void kernel_launch(void* const* d_in, const int* in_sizes, int n_in,
                              void* d_out, int out_size) {
    const float* H = nullptr;
    const float* A = nullptr;
    for (int i = 0; i < n_in; i++) {
        if (in_sizes[i] == N_NODES * C_CLS)        H = (const float*)d_in[i];
        else if (in_sizes[i] == N_NODES * N_NODES) A = (const float*)d_in[i];
    }
    dim3 grid(NBX, NBY);
    mm_fused<<<grid, TPB>>>(A, H, (float*)d_out);
}

// round 6
// speedup vs baseline: 1.7540x; 1.7540x over previous
#include <cuda_runtime.h>
#include <cstdint>

#define N_NODES 8192
#define C_CLS   16
#define ROWS_PER_BLK 256
#define COLS_PER_BLK 256
#define TPB 128
#define NBX (N_NODES / COLS_PER_BLK)   // 32
#define NBY (N_NODES / ROWS_PER_BLK)   // 32
#define NBLK (NBX * NBY)               // 1024

// SoA per-block partials + completion ticket (module-load zeroed; ticket self-resets).
__device__ float g_quadp[NBLK];
__device__ float g_degp[NBLK];
__device__ float g_dHp[C_CLS][NBLK];
__device__ unsigned int g_count;

__global__ void __launch_bounds__(TPB, 8) mm_fused(const float* __restrict__ A,
                                                   const float* __restrict__ H,
                                                   float* __restrict__ out) {
    __shared__ __align__(16) float sh[ROWS_PER_BLK * C_CLS];   // 16 KB H tile
    __shared__ float s_dH[C_CLS];
    __shared__ float s_quad;
    __shared__ float s_deg;
    __shared__ int s_islast;

    const int t = threadIdx.x;
    const int colbase = blockIdx.x * COLS_PER_BLK;
    const int rowbase = blockIdx.y * ROWS_PER_BLK;

    if (t < C_CLS) s_dH[t] = 0.f;
    if (t == 0) { s_quad = 0.f; s_deg = 0.f; s_islast = 0; }

    // Cooperative load of H rows [rowbase, rowbase+256) into SMEM (float4).
    {
        const float4* src = reinterpret_cast<const float4*>(H + (size_t)rowbase * C_CLS);
        float4* dst = reinterpret_cast<float4*>(sh);
        #pragma unroll
        for (int k = 0; k < (ROWS_PER_BLK * C_CLS / 4) / TPB; k++)   // 8
            dst[k * TPB + t] = src[k * TPB + t];
    }
    __syncthreads();

    const int c0 = colbase + 2 * t;   // this lane's two columns: c0, c0+1

    unsigned long long acc0[8], acc1[8];   // packed f32x2: x[c0,:], x[c0+1,:]
    #pragma unroll
    for (int k = 0; k < 8; k++) { acc0[k] = 0ull; acc1[k] = 0ull; }
    float deg0 = 0.f, deg1 = 0.f;

    const float2* __restrict__ arow =
        reinterpret_cast<const float2*>(A + (size_t)rowbase * N_NODES + c0);
    const size_t rs = N_NODES / 2;   // row stride in float2 units

    for (int i = 0; i < ROWS_PER_BLK; i += 4) {
        // Batched loads first: structural MLP = 4 per warp iteration.
        float2 av[4];
        #pragma unroll
        for (int u = 0; u < 4; u++)
            av[u] = __ldg(arow + (size_t)(i + u) * rs);

        #pragma unroll
        for (int u = 0; u < 4; u++) {
            float m0 = (av[u].x > 0.f) ? 1.0f : 0.0f;   // exact {0,1}
            float m1 = (av[u].y > 0.f) ? 1.0f : 0.0f;
            deg0 += m0; deg1 += m1;
            unsigned long long mm0, mm1;
            asm("mov.b64 %0, {%1, %1};" : "=l"(mm0) : "f"(m0));
            asm("mov.b64 %0, {%1, %1};" : "=l"(mm1) : "f"(m1));
            const ulonglong2* hp =
                reinterpret_cast<const ulonglong2*>(sh + (i + u) * C_CLS);
            #pragma unroll
            for (int k = 0; k < 4; k++) {
                ulonglong2 h = hp[k];   // LDS.128, warp-uniform broadcast
                asm("fma.rn.f32x2 %0, %1, %2, %0;" : "+l"(acc0[2*k])   : "l"(h.x), "l"(mm0));
                asm("fma.rn.f32x2 %0, %1, %2, %0;" : "+l"(acc0[2*k+1]) : "l"(h.y), "l"(mm0));
                asm("fma.rn.f32x2 %0, %1, %2, %0;" : "+l"(acc1[2*k])   : "l"(h.x), "l"(mm1));
                asm("fma.rn.f32x2 %0, %1, %2, %0;" : "+l"(acc1[2*k+1]) : "l"(h.y), "l"(mm1));
            }
        }
    }

    // ---- Epilogue: quad += x[j].H[j] ; dH += deg_j * H[j,:] ----
    const float* __restrict__ h0 = H + (size_t)c0 * C_CLS;
    const float* __restrict__ h1 = h0 + C_CLS;
    float q = 0.f;
    #pragma unroll
    for (int k = 0; k < 8; k++) {
        float x0lo = __uint_as_float((unsigned int)(acc0[k] & 0xffffffffull));
        float x0hi = __uint_as_float((unsigned int)(acc0[k] >> 32));
        float x1lo = __uint_as_float((unsigned int)(acc1[k] & 0xffffffffull));
        float x1hi = __uint_as_float((unsigned int)(acc1[k] >> 32));
        q += x0lo * h0[2*k] + x0hi * h0[2*k + 1];
        q += x1lo * h1[2*k] + x1hi * h1[2*k + 1];
    }
    atomicAdd(&s_quad, q);
    atomicAdd(&s_deg, deg0 + deg1);
    #pragma unroll
    for (int k = 0; k < C_CLS; k++)
        atomicAdd(&s_dH[k], deg0 * h0[k] + deg1 * h1[k]);
    __syncthreads();

    // ---- Publish partials, then last-block ticket ----
    const int bid = blockIdx.y * gridDim.x + blockIdx.x;
    if (t == 0) { g_quadp[bid] = s_quad; g_degp[bid] = s_deg; }
    if (t < C_CLS) g_dHp[t][bid] = s_dH[t];
    __threadfence();
    if (t == 0) {
        unsigned int ticket = atomicAdd(&g_count, 1u);
        s_islast = (ticket == NBLK - 1);
    }
    __syncthreads();
    if (!s_islast) return;

    // ---- Last block: final reduction over all 1024 partials ----
    __threadfence();
    __shared__ double r_acc[C_CLS + 2];
    if (t < C_CLS + 2) r_acc[t] = 0.0;
    __syncthreads();

    double lq = 0.0, ls = 0.0, ldh[C_CLS];
    #pragma unroll
    for (int k = 0; k < C_CLS; k++) ldh[k] = 0.0;
    for (int slot = t; slot < NBLK; slot += TPB) {   // coalesced SoA reads
        lq += (double)g_quadp[slot];
        ls += (double)g_degp[slot];
        #pragma unroll
        for (int k = 0; k < C_CLS; k++) ldh[k] += (double)g_dHp[k][slot];
    }
    #pragma unroll
    for (int o = 16; o > 0; o >>= 1) {
        lq += __shfl_xor_sync(0xffffffffu, lq, o);
        ls += __shfl_xor_sync(0xffffffffu, ls, o);
        #pragma unroll
        for (int k = 0; k < C_CLS; k++)
            ldh[k] += __shfl_xor_sync(0xffffffffu, ldh[k], o);
    }
    if ((t & 31) == 0) {
        atomicAdd(&r_acc[0], lq);
        atomicAdd(&r_acc[1], ls);
        #pragma unroll
        for (int k = 0; k < C_CLS; k++) atomicAdd(&r_acc[2 + k], ldh[k]);
    }
    __syncthreads();
    if (t == 0) {
        double quad = r_acc[0], s = r_acc[1], d = 0.0;
        #pragma unroll
        for (int k = 0; k < C_CLS; k++) d += r_acc[2 + k] * r_acc[2 + k];
        out[0] = (float)((quad - d / s) / s);
        g_count = 0;   // reset for next graph replay
    }
}

extern "C" void kernel_launch(void* const* d_in, const int* in_sizes, int n_in,
                              void* d_out, int out_size) {
    const float* H = nullptr;
    const float* A = nullptr;
    for (int i = 0; i < n_in; i++) {
        if (in_sizes[i] == N_NODES * C_CLS)        H = (const float*)d_in[i];
        else if (in_sizes[i] == N_NODES * N_NODES) A = (const float*)d_in[i];
    }
    dim3 grid(NBX, NBY);
    mm_fused<<<grid, TPB>>>(A, H, (float*)d_out);
}